// round 16
// baseline (speedup 1.0000x reference)
#include <cuda_runtime.h>

// BinsChamferLoss: n=16, d=128, h=192, w=256.  Two kernels + PDL overlap.
// out[b] = (loss1[b] + loss2[b]) / sum(valid_mask)   (count over ALL batches)
//   g = valid ? max(t, bins[b][0]) : bins[b][0]
//   loss1[b] = sum_pixels min_bins |g - bin|   (uniform LUT + short scan)
//   loss2[b] = sum_bins  min_pixels |g - bin|  (per-batch segment extrema via
//                                               REDG + parallel scans)
//
// R16: fin was a serial ~3-4us node after main. With single-wave main (128
// blocks) + fin (16 blocks) = 144 <= 148 SMs, Programmatic Dependent Launch
// makes fin co-resident: it launches at main's start-trigger, preloads bins,
// and parks in cudaGridDependencySynchronize() until main completes — hiding
// fin's launch+prolog entirely. All scratch reads in fin are AFTER the sync.

#define NB   16
#define DB   128
#define HW   49152            // 192*256
#define BPB  8                // blocks per batch -> grid 128 = single wave
#define PPB  (HW / BPB)       // 6144 pixels per block
#define TH   512
#define NPX  3                // float4 chunks per thread (3*4 = 12 px)
#define TFIN 256
#define NSEG (DB + 1)         // segment s in [1,128]; slot 0 unused
#define LUTN 1024
#define INF_BITS 0x7F800000

// Per-batch segment extrema; 0 = empty (zero .bss start, reset by fin).
__device__ int          g_bmax[NB * NSEG];   // float bits of segment max
__device__ int          g_bmin[NB * NSEG];   // 0x7FFFFFFF - float bits of min
// Per-block sums (plain stores, fully overwritten every replay).
__device__ float        g_pl1 [NB * BPB];
__device__ unsigned int g_pcnt[NB * BPB];
// Stage-2 scratch (written before read each replay; ticket resets to 0).
__device__ float        g_bsum[NB];
__device__ unsigned int g_bcnt[NB];
__device__ unsigned int g_tick_g;

__global__ __launch_bounds__(TH, 1) void bcl_main(const float* __restrict__ bins,
                                                  const float* __restrict__ tdm,
                                                  const int*   __restrict__ mask) {
    // Fire the PDL trigger immediately: all 128 CTAs are wave-1 resident, so
    // fin launches right away and overlaps its prolog with our whole runtime.
    cudaTriggerProgrammaticLaunchCompletion();

    const int batch = blockIdx.x / BPB;
    const int blk   = blockIdx.x % BPB;
    const int bid   = blockIdx.x;
    const int tid   = threadIdx.x;

    // ---- front-batch ALL pixel loads (MLP=6), hidden under the prolog.
    const int base = batch * HW + blk * PPB;
    const float4* t4 = (const float4*)(tdm + base);
    const int4*   m4 = (const int4*)(mask + base);
    float4 tv[NPX]; int4 mv[NPX];
    #pragma unroll
    for (int c = 0; c < NPX; c++) {
        tv[c] = t4[c * TH + tid];
        mv[c] = m4[c * TH + tid];
    }

    __shared__ float sb[NSEG];          // sorted bins + inf pad
    __shared__ int   lut[LUTN];         // lut[q] = upper_bound(edge_q) in [1,128]
    __shared__ int   spmax[NSEG];
    __shared__ int   spmin[NSEG];
    __shared__ int   sflag;             // any invalid pixel seen
    __shared__ float        wl[TH / 32];
    __shared__ unsigned int wc[TH / 32];

    if (tid < DB)   sb[tid] = bins[batch * DB + tid];
    if (tid == DB)  sb[DB]  = __int_as_float(INF_BITS);
    if (tid < NSEG) { spmax[tid] = -1; spmin[tid] = INF_BITS; }
    if (tid == 0) sflag = 0;
    __syncthreads();

    const float b0       = sb[0];
    const float lutHi    = fmaxf(10.0f, sb[DB - 1]) + 1e-3f;
    const float lutScale = (float)LUTN / (lutHi - b0);
    const float invScale = (lutHi - b0) * (1.0f / (float)LUTN);

    // lut[q] = first s with sb[s] > edge_q, edge_q = b0 + q*invScale  (s >= 1).
    #pragma unroll
    for (int qq = 0; qq < LUTN / TH; qq++) {
        const int q = qq * TH + tid;
        const float edge = b0 + (float)q * invScale;
        int lo = 0, hi = DB;
        #pragma unroll
        for (int bs = 0; bs < 8; bs++) {
            const int mid = (lo + hi) >> 1;
            if (sb[mid] <= edge) lo = mid + 1; else hi = mid;
        }
        lut[q] = lo;
    }
    __syncthreads();

    float loss1 = 0.0f;
    unsigned int cnt = 0;
    bool sawInvalid = false;

    #pragma unroll
    for (int c = 0; c < NPX; c++) {
        const float gv[4] = {tv[c].x, tv[c].y, tv[c].z, tv[c].w};
        const int   mk[4] = {mv[c].x, mv[c].y, mv[c].z, mv[c].w};
        #pragma unroll
        for (int k = 0; k < 4; k++) {
            const bool valid = (mk[k] != 0);
            const float g = valid ? fmaxf(gv[k], b0) : b0;   // invalid: g=b0, dist 0
            int q = (int)((g - b0) * lutScale);
            q = max(0, min(LUTN - 1, q));
            int s = lut[q];
            float hiv = sb[s];
            while (hiv <= g) hiv = sb[++s];              // ~0.13 extra iters avg
            loss1 += fminf(g - sb[s - 1], hiv - g);      // exactly 0 when invalid
            cnt += valid ? 1u : 0u;
            sawInvalid |= !valid;
            const int gi = __float_as_int(g);            // g>0: int order==float order
            if (valid && gi > spmax[s]) atomicMax(&spmax[s], gi);  // monotonic: safe
            if (valid && gi < spmin[s]) atomicMin(&spmin[s], gi);
        }
    }
    if (sawInvalid) sflag = 1;                           // benign race
    __syncthreads();

    if (tid == 0 && sflag) {             // one b0 segment update for all invalids
        int s = 1;
        while (sb[s] <= b0) s++;
        const int bi = __float_as_int(b0);
        if (bi > spmax[s]) atomicMax(&spmax[s], bi);
        if (bi < spmin[s]) atomicMin(&spmin[s], bi);
    }

    // block reduce loss1 & count
    #pragma unroll
    for (int off = 16; off; off >>= 1) {
        loss1 += __shfl_down_sync(0xFFFFFFFFu, loss1, off);
        cnt   += __shfl_down_sync(0xFFFFFFFFu, cnt,   off);
    }
    if ((tid & 31) == 0) { wl[tid >> 5] = loss1; wc[tid >> 5] = cnt; }
    __syncthreads();

    // publish: sums as plain stores; segment extrema as fire-and-forget REDG
    // into per-batch tables (0 = empty; min flipped so atomicMax does min).
    if (tid == 0) {
        float L = 0.0f; unsigned int C = 0;
        #pragma unroll
        for (int w = 0; w < TH / 32; w++) { L += wl[w]; C += wc[w]; }
        g_pl1[bid] = L; g_pcnt[bid] = C;
    }
    if (tid < NSEG) {
        const int mx = spmax[tid];
        if (mx != -1)       atomicMax(&g_bmax[batch * NSEG + tid], mx);
        const int mn = spmin[tid];
        if (mn != INF_BITS) atomicMax(&g_bmin[batch * NSEG + tid], 0x7FFFFFFF - mn);
    }
}

__global__ __launch_bounds__(TFIN) void bcl_fin(const float* __restrict__ bins,
                                                float* __restrict__ out) {
    const int batch = blockIdx.x;
    const int tid   = threadIdx.x;

    __shared__ float sb[NSEG];
    __shared__ float pref[NSEG], suf[NSEG];
    __shared__ float        wl[TFIN / 32];
    __shared__ unsigned int wc[TFIN / 32];

    // Independent prolog (input-only) — overlaps with main under PDL.
    if (tid < DB)  sb[tid] = bins[batch * DB + tid];
    if (tid == DB) sb[DB]  = __int_as_float(INF_BITS);

    // Wait for main's completion; all its global writes become visible.
    cudaGridDependencySynchronize();

    if (tid < NSEG) {                    // coalesced per-batch reads + reset to 0
        const int idx = batch * NSEG + tid;
        const int mx  = g_bmax[idx];
        const int mn2 = g_bmin[idx];
        g_bmax[idx] = 0;                 // clean state for next graph replay
        g_bmin[idx] = 0;
        pref[tid] = (mx  == 0) ? -1e30f : __int_as_float(mx);
        suf [tid] = (mn2 == 0) ?  1e30f : __int_as_float(0x7FFFFFFF - mn2);
    }
    float L = 0.0f; unsigned int C = 0;
    if (tid < 32) {
        if (tid < BPB) { L = g_pl1[batch * BPB + tid]; C = g_pcnt[batch * BPB + tid]; }
        #pragma unroll
        for (int off = 16; off; off >>= 1) {
            L += __shfl_down_sync(0xFFFFFFFFu, L, off);
            C += __shfl_down_sync(0xFFFFFFFFu, C, off);
        }
    }
    if (tid == 0) { wl[0] = L; wc[0] = C; }
    __syncthreads();

    // Parallel scans: pref = inclusive prefix-max, suf = inclusive suffix-min.
    #pragma unroll
    for (int off = 1; off < NSEG; off <<= 1) {           // 8 Hillis-Steele steps
        float a = 0.0f, bmn = 0.0f;
        if (tid < NSEG) {
            a = pref[tid];
            if (tid >= off) a = fmaxf(a, pref[tid - off]);
            bmn = suf[tid];
            if (tid + off < NSEG) bmn = fminf(bmn, suf[tid + off]);
        }
        __syncthreads();
        if (tid < NSEG) { pref[tid] = a; suf[tid] = bmn; }
        __syncthreads();
    }

    float v = 0.0f;
    if (tid < DB) {
        const float bj = sb[tid];
        v = fminf(bj - pref[tid], suf[tid + 1] - bj);    // exact per-bin min dist
    }
    #pragma unroll
    for (int off = 16; off; off >>= 1) v += __shfl_down_sync(0xFFFFFFFFu, v, off);
    __shared__ float wv[TFIN / 32];
    if ((tid & 31) == 0) wv[tid >> 5] = v;
    __syncthreads();

    if (tid == 0) {
        const float loss2 = wv[0] + wv[1] + wv[2] + wv[3];
        g_bsum[batch] = wl[0] + loss2;
        g_bcnt[batch] = wc[0];
        __threadfence();
        const unsigned int t2 = atomicAdd(&g_tick_g, 1u);
        if (t2 == NB - 1) {                              // last of 16 blocks
            g_tick_g = 0;
            __threadfence();
            unsigned int tot = 0;
            #pragma unroll
            for (int b = 0; b < NB; b++) tot += g_bcnt[b];
            const float inv = 1.0f / (float)tot;
            #pragma unroll
            for (int b = 0; b < NB; b++) out[b] = g_bsum[b] * inv;
        }
    }
}

extern "C" void kernel_launch(void* const* d_in, const int* in_sizes, int n_in,
                              void* d_out, int out_size) {
    const float* bins = (const float*)d_in[0];
    const float* tdm  = (const float*)d_in[1];
    const int*   msk  = (const int*)d_in[2];
    float*       out  = (float*)d_out;

    bcl_main<<<NB * BPB, TH>>>(bins, tdm, msk);

    // fin: programmatic dependent launch — may start during bcl_main; its
    // cudaGridDependencySynchronize() provides the ordering + visibility.
    cudaLaunchConfig_t cfg = {};
    cfg.gridDim  = dim3(NB);
    cfg.blockDim = dim3(TFIN);
    cfg.dynamicSmemBytes = 0;
    cfg.stream = 0;
    cudaLaunchAttribute attrs[1];
    attrs[0].id = cudaLaunchAttributeProgrammaticStreamSerialization;
    attrs[0].val.programmaticStreamSerializationAllowed = 1;
    cfg.attrs = attrs;
    cfg.numAttrs = 1;
    cudaLaunchKernelEx(&cfg, bcl_fin, bins, out);
}

// round 17
// speedup vs baseline: 1.0245x; 1.0245x over previous
#include <cuda_runtime.h>

// BinsChamferLoss: n=16, d=128, h=192, w=256.  Two-kernel pipeline (R14 base).
// out[b] = (loss1[b] + loss2[b]) / sum(valid_mask)   (count over ALL batches)
//   g = valid ? max(t, bins[b][0]) : bins[b][0]
//   loss1[b] = sum_pixels min_bins |g - bin|   (uniform LUT + short scan)
//   loss2[b] = sum_bins  min_pixels |g - bin|  (per-batch segment extrema via
//                                               REDG + parallel scans)
//
// R17: cut smem gathers/pixel 5 -> 3 with 8-byte paired tables:
//   sbp[s]  = float2(sb[s-1], sb[s])  -> one LDS.64 for both distance operands
//   spmm[s] = int2(max_bits, min_bits)-> one LDS.64 guard read for both extrema
// (R13's float4 attempt widened gathers to 16B and regressed; 8B keeps the
// 2-phase gather floor.)  PDL dropped (R16: neutral).

#define NB   16
#define DB   128
#define HW   49152            // 192*256
#define BPB  24               // blocks per batch
#define PPB  (HW / BPB)       // 2048 pixels per block
#define TH   512              // 4 pixels per thread
#define TFIN 256
#define NSEG (DB + 1)         // segment s in [1,128]; slot 0 unused
#define LUTN 1024
#define INF_BITS 0x7F800000

// Per-batch segment extrema; 0 = empty (zero .bss start, reset by fin).
__device__ int          g_bmax[NB * NSEG];   // float bits of segment max
__device__ int          g_bmin[NB * NSEG];   // 0x7FFFFFFF - float bits of min
// Per-block sums (plain stores, fully overwritten every replay).
__device__ float        g_pl1 [NB * BPB];
__device__ unsigned int g_pcnt[NB * BPB];
// Stage-2 scratch (written before read each replay; ticket resets to 0).
__device__ float        g_bsum[NB];
__device__ unsigned int g_bcnt[NB];
__device__ unsigned int g_tick_g;

__global__ __launch_bounds__(TH, 1) void bcl_main(const float* __restrict__ bins,
                                                  const float* __restrict__ tdm,
                                                  const int*   __restrict__ mask) {
    const int batch = blockIdx.x / BPB;
    const int blk   = blockIdx.x % BPB;
    const int bid   = blockIdx.x;
    const int tid   = threadIdx.x;

    // ---- pixel loads first: DRAM latency hides under the prolog.
    const int base = batch * HW + blk * PPB;
    const float4 tv = ((const float4*)(tdm + base))[tid];   // 4 px/thread
    const int4   mv = ((const int4*)(mask + base))[tid];

    __shared__ float  sb[NSEG];         // sorted bins + inf pad
    __shared__ float2 sbp[NSEG];        // sbp[s] = (sb[s-1], sb[s]),  s in [1,128]
    __shared__ int    lut[LUTN];        // lut[q] = upper_bound(edge_q) in [1,128]
    __shared__ int2   spmm[NSEG];       // .x = max bits (-1 empty), .y = min bits
    __shared__ int    sflag;            // any invalid pixel seen
    __shared__ float        wl[TH / 32];
    __shared__ unsigned int wc[TH / 32];

    if (tid < DB)   sb[tid] = bins[batch * DB + tid];
    if (tid == DB)  sb[DB]  = __int_as_float(INF_BITS);
    if (tid < NSEG) spmm[tid] = make_int2(-1, INF_BITS);
    if (tid == 0) sflag = 0;
    __syncthreads();

    const float b0       = sb[0];
    const float lutHi    = fmaxf(10.0f, sb[DB - 1]) + 1e-3f;
    const float lutScale = (float)LUTN / (lutHi - b0);
    const float invScale = (lutHi - b0) * (1.0f / (float)LUTN);

    if (tid >= 1 && tid < NSEG)          // paired bins table
        sbp[tid] = make_float2(sb[tid - 1], sb[tid]);

    // lut[q] = first s with sb[s] > edge_q, edge_q = b0 + q*invScale  (s >= 1).
    #pragma unroll
    for (int qq = 0; qq < LUTN / TH; qq++) {
        const int q = qq * TH + tid;
        const float edge = b0 + (float)q * invScale;
        int lo = 0, hi = DB;
        #pragma unroll
        for (int bs = 0; bs < 8; bs++) {
            const int mid = (lo + hi) >> 1;
            if (sb[mid] <= edge) lo = mid + 1; else hi = mid;
        }
        lut[q] = lo;
    }
    __syncthreads();

    float loss1 = 0.0f;
    unsigned int cnt = 0;
    bool sawInvalid = false;

    const float gv[4] = {tv.x, tv.y, tv.z, tv.w};
    const int   mk[4] = {mv.x, mv.y, mv.z, mv.w};

    #pragma unroll
    for (int k = 0; k < 4; k++) {
        const bool valid = (mk[k] != 0);
        const float g = valid ? fmaxf(gv[k], b0) : b0;   // invalid -> g=b0, dist 0
        int q = (int)((g - b0) * lutScale);
        q = max(0, min(LUTN - 1, q));
        int s = lut[q];
        float2 c = sbp[s];                               // ONE LDS.64: (lo, hi)
        while (c.y <= g) c = sbp[++s];                   // ~0.13 extra iters avg
        loss1 += fminf(g - c.x, c.y - g);                // exactly 0 when invalid
        cnt += valid ? 1u : 0u;
        sawInvalid |= !valid;
        const int gi = __float_as_int(g);                // g>0: int order==float order
        if (valid) {
            const int2 mm = spmm[s];                     // ONE LDS.64 guard read
            if (gi > mm.x) atomicMax(&spmm[s].x, gi);    // monotonic: race-safe
            if (gi < mm.y) atomicMin(&spmm[s].y, gi);
        }
    }
    if (sawInvalid) sflag = 1;                           // benign race
    __syncthreads();

    if (tid == 0 && sflag) {             // one b0 segment update for all invalids
        int s = 1;
        while (sb[s] <= b0) s++;
        const int bi = __float_as_int(b0);
        if (bi > spmm[s].x) atomicMax(&spmm[s].x, bi);
        if (bi < spmm[s].y) atomicMin(&spmm[s].y, bi);
    }

    // block reduce loss1 & count
    #pragma unroll
    for (int off = 16; off; off >>= 1) {
        loss1 += __shfl_down_sync(0xFFFFFFFFu, loss1, off);
        cnt   += __shfl_down_sync(0xFFFFFFFFu, cnt,   off);
    }
    if ((tid & 31) == 0) { wl[tid >> 5] = loss1; wc[tid >> 5] = cnt; }
    __syncthreads();

    // publish: sums as plain stores; segment extrema as fire-and-forget REDG
    // into per-batch tables (0 = empty; min flipped so atomicMax does min).
    if (tid == 0) {
        float L = 0.0f; unsigned int C = 0;
        #pragma unroll
        for (int w = 0; w < TH / 32; w++) { L += wl[w]; C += wc[w]; }
        g_pl1[bid] = L; g_pcnt[bid] = C;
    }
    if (tid < NSEG) {
        const int2 mm = spmm[tid];
        if (mm.x != -1)       atomicMax(&g_bmax[batch * NSEG + tid], mm.x);
        if (mm.y != INF_BITS) atomicMax(&g_bmin[batch * NSEG + tid], 0x7FFFFFFF - mm.y);
    }
}

__global__ __launch_bounds__(TFIN) void bcl_fin(const float* __restrict__ bins,
                                                float* __restrict__ out) {
    const int batch = blockIdx.x;
    const int tid   = threadIdx.x;

    __shared__ float sb[NSEG];
    __shared__ float pref[NSEG], suf[NSEG];
    __shared__ float        wl[TFIN / 32];
    __shared__ unsigned int wc[TFIN / 32];

    if (tid < DB)  sb[tid] = bins[batch * DB + tid];
    if (tid == DB) sb[DB]  = __int_as_float(INF_BITS);

    if (tid < NSEG) {                    // coalesced per-batch reads + reset to 0
        const int idx = batch * NSEG + tid;
        const int mx  = g_bmax[idx];
        const int mn2 = g_bmin[idx];
        g_bmax[idx] = 0;                 // clean state for next graph replay
        g_bmin[idx] = 0;
        pref[tid] = (mx  == 0) ? -1e30f : __int_as_float(mx);
        suf [tid] = (mn2 == 0) ?  1e30f : __int_as_float(0x7FFFFFFF - mn2);
    }
    float L = 0.0f; unsigned int C = 0;
    if (tid < 32) {
        if (tid < BPB) { L = g_pl1[batch * BPB + tid]; C = g_pcnt[batch * BPB + tid]; }
        #pragma unroll
        for (int off = 16; off; off >>= 1) {
            L += __shfl_down_sync(0xFFFFFFFFu, L, off);
            C += __shfl_down_sync(0xFFFFFFFFu, C, off);
        }
    }
    if (tid == 0) { wl[0] = L; wc[0] = C; }
    __syncthreads();

    // Parallel scans: pref = inclusive prefix-max, suf = inclusive suffix-min.
    #pragma unroll
    for (int off = 1; off < NSEG; off <<= 1) {           // 8 Hillis-Steele steps
        float a = 0.0f, bmn = 0.0f;
        if (tid < NSEG) {
            a = pref[tid];
            if (tid >= off) a = fmaxf(a, pref[tid - off]);
            bmn = suf[tid];
            if (tid + off < NSEG) bmn = fminf(bmn, suf[tid + off]);
        }
        __syncthreads();
        if (tid < NSEG) { pref[tid] = a; suf[tid] = bmn; }
        __syncthreads();
    }

    float v = 0.0f;
    if (tid < DB) {
        const float bj = sb[tid];
        v = fminf(bj - pref[tid], suf[tid + 1] - bj);    // exact per-bin min dist
    }
    #pragma unroll
    for (int off = 16; off; off >>= 1) v += __shfl_down_sync(0xFFFFFFFFu, v, off);
    __shared__ float wv[TFIN / 32];
    if ((tid & 31) == 0) wv[tid >> 5] = v;
    __syncthreads();

    if (tid == 0) {
        const float loss2 = wv[0] + wv[1] + wv[2] + wv[3];
        g_bsum[batch] = wl[0] + loss2;
        g_bcnt[batch] = wc[0];
        __threadfence();
        const unsigned int t2 = atomicAdd(&g_tick_g, 1u);
        if (t2 == NB - 1) {                              // last of 16 blocks
            g_tick_g = 0;
            __threadfence();
            unsigned int tot = 0;
            #pragma unroll
            for (int b = 0; b < NB; b++) tot += g_bcnt[b];
            const float inv = 1.0f / (float)tot;
            #pragma unroll
            for (int b = 0; b < NB; b++) out[b] = g_bsum[b] * inv;
        }
    }
}

extern "C" void kernel_launch(void* const* d_in, const int* in_sizes, int n_in,
                              void* d_out, int out_size) {
    const float* bins = (const float*)d_in[0];
    const float* tdm  = (const float*)d_in[1];
    const int*   msk  = (const int*)d_in[2];
    float*       out  = (float*)d_out;

    bcl_main<<<NB * BPB, TH>>>(bins, tdm, msk);
    bcl_fin<<<NB, TFIN>>>(bins, out);
}